// round 5
// baseline (speedup 1.0000x reference)
#include <cuda_runtime.h>
#include <cstdint>

// Elementwise: y = min(((x + 1) * 0.75)^2, 10) over 8192*8192 fp32.
// HBM-bound streaming at the R+W bandwidth ceiling. 512 threads/block,
// 4 independent front-batched LDG.128 per thread, no bounds predicates
// on the exact-size path, streaming cache hints (zero reuse).

#define THREADS 512
#define UNROLL  4

__device__ __forceinline__ float4 f4map(float4 v)
{
    float t0 = (v.x + 1.0f) * 0.75f;
    float t1 = (v.y + 1.0f) * 0.75f;
    float t2 = (v.z + 1.0f) * 0.75f;
    float t3 = (v.w + 1.0f) * 0.75f;
    float4 r;
    r.x = fminf(t0 * t0, 10.0f);
    r.y = fminf(t1 * t1, 10.0f);
    r.z = fminf(t2 * t2, 10.0f);
    r.w = fminf(t3 * t3, 10.0f);
    return r;
}

// Exact path: grid * THREADS * UNROLL == n4. No predicates.
__global__ __launch_bounds__(THREADS) void elemwise_exact(
    const float4* __restrict__ x, float4* __restrict__ y)
{
    int base = blockIdx.x * (THREADS * UNROLL) + threadIdx.x;

    float4 v[UNROLL];
#pragma unroll
    for (int k = 0; k < UNROLL; k++)
        v[k] = __ldcs(&x[base + k * THREADS]);

#pragma unroll
    for (int k = 0; k < UNROLL; k++)
        __stcs(&y[base + k * THREADS], f4map(v[k]));
}

// Predicated fallback for non-dividing sizes (not taken for 8192x8192).
__global__ __launch_bounds__(THREADS) void elemwise_pred(
    const float4* __restrict__ x, float4* __restrict__ y, int n4)
{
    int base = blockIdx.x * (THREADS * UNROLL) + threadIdx.x;
#pragma unroll
    for (int k = 0; k < UNROLL; k++) {
        int i = base + k * THREADS;
        if (i < n4) __stcs(&y[i], f4map(__ldcs(&x[i])));
    }
}

extern "C" void kernel_launch(void* const* d_in, const int* in_sizes, int n_in,
                              void* d_out, int out_size)
{
    const float4* x = (const float4*)d_in[0];
    float4* y = (float4*)d_out;
    int n = in_sizes[0];               // 67108864
    int n4 = n >> 2;                   // 16777216 float4
    int per_block = THREADS * UNROLL;  // 2048

    if (n4 % per_block == 0) {
        elemwise_exact<<<n4 / per_block, THREADS>>>(x, y);   // 8192 blocks
    } else {
        elemwise_pred<<<(n4 + per_block - 1) / per_block, THREADS>>>(x, y, n4);
    }
}